// round 2
// baseline (speedup 1.0000x reference)
#include <cuda_runtime.h>
#include <cuda_bf16.h>
#include <math.h>

// ---------------------------------------------------------------------------
// Problem constants
// ---------------------------------------------------------------------------
#define NLEV 16
#define TSZ  (1 << 19)          // hash table entries per level
#define TMASK (TSZ - 1)
#define HASH_PRIME 2654435761u

typedef unsigned long long u64;

// Weights staged into constant memory (padded for 8B-aligned f32x2 pairs)
struct __align__(16) Weights {
    float wp1[12 * 64];     // (12,64) row-major
    float wp2[64 * 64];     // (64,64)
    float wp3[64];
    float wt [32 * 66];     // (32,65) padded to stride 66 so every row's pairs are 8B aligned
    float bt [66];          // 65 + pad
};
__device__   Weights g_w;   // staging (written by prep kernel)
__constant__ Weights c_w;   // fast uniform access

struct LevelP {
    float scale[NLEV];
    int   res[NLEV];
    int   dense[NLEV];
};

// ---------------------------------------------------------------------------
// f32x2 helpers (packed dual-FMA; ptxas never emits FFMA2 from C++)
// ---------------------------------------------------------------------------
__device__ __forceinline__ u64 pack2(float a, float b) {
    u64 r; asm("mov.b64 %0, {%1, %2};" : "=l"(r) : "f"(a), "f"(b)); return r;
}
__device__ __forceinline__ u64 dup2(float a) { return pack2(a, a); }
__device__ __forceinline__ void unpack2(u64 v, float &a, float &b) {
    asm("mov.b64 {%0, %1}, %2;" : "=f"(a), "=f"(b) : "l"(v));
}
__device__ __forceinline__ void fma2(u64 &d, u64 a, u64 b) {
    asm("fma.rn.f32x2 %0, %1, %2, %0;" : "+l"(d) : "l"(a), "l"(b));
}

__device__ __forceinline__ float sigm(float x) {
    return __fdividef(1.0f, 1.0f + __expf(-x));
}

// ---------------------------------------------------------------------------
// Prep kernel: rearrange weights into padded layout in g_w (then D2D -> c_w)
// ---------------------------------------------------------------------------
__global__ void prep_weights(const float* __restrict__ W_tiny,
                             const float* __restrict__ b_tiny,
                             const float* __restrict__ Wp1,
                             const float* __restrict__ Wp2,
                             const float* __restrict__ Wp3) {
    int t = threadIdx.x;
    for (int i = t; i < 12 * 64; i += blockDim.x) g_w.wp1[i] = Wp1[i];
    for (int i = t; i < 64 * 64; i += blockDim.x) g_w.wp2[i] = Wp2[i];
    if (t < 64) g_w.wp3[t] = Wp3[t];
    for (int i = t; i < 32 * 66; i += blockDim.x) {
        int k = i / 66, j = i % 66;
        g_w.wt[i] = (j < 65) ? W_tiny[k * 65 + j] : 0.0f;
    }
    if (t < 66) g_w.bt[t] = (t < 65) ? b_tiny[t] : 0.0f;
}

// ---------------------------------------------------------------------------
// Main fused kernel: one point per thread, 128-point tile per block
// ---------------------------------------------------------------------------
__global__ void __launch_bounds__(128)
sdf_kernel(const float* __restrict__ inputs,
           const float* __restrict__ tables,
           float* __restrict__ out,
           int N, LevelP P) {
    __shared__ float so[128 * 65];   // input staging, then output staging

    const int tid  = threadIdx.x;
    const int base = blockIdx.x * 128;
    const int cnt  = min(128, N - base);

    // ---- cooperative, coalesced input load (3 floats/point) ----
    for (int t = tid; t < cnt * 3; t += 128) so[t] = inputs[(size_t)base * 3 + t];
    __syncthreads();
    float x = 0.f, y = 0.f, z = 0.f;
    if (tid < cnt) { x = so[tid * 3]; y = so[tid * 3 + 1]; z = so[tid * 3 + 2]; }
    __syncthreads();   // so is reused for output staging below

    // =======================================================================
    // PHASE 1: prior_net (frequency encoding + 12->64->64->1 MLP)
    // =======================================================================
    const float PIF = 3.14159265358979323846f;
    float enc[12];
    {
        float s, c;
        sincosf(x * PIF,          &s, &c); enc[0] = s; enc[3]  = c;
        sincosf(x * (2.0f * PIF), &s, &c); enc[1] = s; enc[4]  = c;
        sincosf(x * (4.0f * PIF), &s, &c); enc[2] = s; enc[5]  = c;
        sincosf(y * PIF,          &s, &c); enc[6] = s; enc[9]  = c;
        sincosf(y * (2.0f * PIF), &s, &c); enc[7] = s; enc[10] = c;
        sincosf(y * (4.0f * PIF), &s, &c); enc[8] = s; enc[11] = c;
    }

    float h1[64];
    {
        u64 acc[32];
        #pragma unroll
        for (int jp = 0; jp < 32; jp++) acc[jp] = 0ull;
        const u64* w1 = reinterpret_cast<const u64*>(c_w.wp1);
        #pragma unroll
        for (int i = 0; i < 12; i++) {
            u64 e = dup2(enc[i]);
            #pragma unroll
            for (int jp = 0; jp < 32; jp++) fma2(acc[jp], e, w1[i * 32 + jp]);
        }
        #pragma unroll
        for (int jp = 0; jp < 32; jp++) {
            float a, b; unpack2(acc[jp], a, b);
            h1[2 * jp]     = sigm(a);
            h1[2 * jp + 1] = sigm(b);
        }
    }

    float prior = 0.0f;
    {
        const u64* w2 = reinterpret_cast<const u64*>(c_w.wp2);
        #pragma unroll
        for (int c = 0; c < 2; c++) {          // two chunks of 32 neurons
            u64 a2[16];
            #pragma unroll
            for (int jp = 0; jp < 16; jp++) a2[jp] = 0ull;
            #pragma unroll
            for (int k = 0; k < 64; k++) {
                u64 hk = dup2(h1[k]);
                #pragma unroll
                for (int jp = 0; jp < 16; jp++)
                    fma2(a2[jp], hk, w2[k * 32 + c * 16 + jp]);
            }
            #pragma unroll
            for (int jp = 0; jp < 16; jp++) {
                float a, b; unpack2(a2[jp], a, b);
                int j = c * 32 + 2 * jp;
                prior += sigm(a) * c_w.wp3[j] + sigm(b) * c_w.wp3[j + 1];
            }
        }
    }

    // =======================================================================
    // PHASE 2: multires hash-grid encode (16 levels, bilinear)
    // =======================================================================
    float feat[32];
    {
        const float u = __fadd_rn(__fdiv_rn(x, 30.0f), 0.5f);
        const float v = __fadd_rn(__fdiv_rn(y, 30.0f), 0.5f);
        const float2* tb = reinterpret_cast<const float2*>(tables);
        #pragma unroll
        for (int l = 0; l < NLEV; l++) {
            float s  = P.scale[l];
            float px = __fadd_rn(__fmul_rn(u, s), 0.5f);
            float py = __fadd_rn(__fmul_rn(v, s), 0.5f);
            float fx = floorf(px), fy = floorf(py);
            float wx = px - fx,    wy = py - fy;
            int ix = (int)fx, iy = (int)fy;
            int i00, i10, i01, i11;
            if (P.dense[l]) {
                int r = P.res[l];
                i00 = ix + iy * r;  i10 = i00 + 1;
                i01 = i00 + r;      i11 = i01 + 1;
                // JAX gather clips OOB indices
                i00 = min(max(i00, 0), TSZ - 1);
                i10 = min(max(i10, 0), TSZ - 1);
                i01 = min(max(i01, 0), TSZ - 1);
                i11 = min(max(i11, 0), TSZ - 1);
            } else {
                unsigned ux = (unsigned)ix, uy = (unsigned)iy;
                unsigned hy0 = uy * HASH_PRIME;
                unsigned hy1 = (uy + 1u) * HASH_PRIME;
                i00 = (int)((ux        ^ hy0) & TMASK);
                i10 = (int)(((ux + 1u) ^ hy0) & TMASK);
                i01 = (int)((ux        ^ hy1) & TMASK);
                i11 = (int)(((ux + 1u) ^ hy1) & TMASK);
            }
            const float2* t = tb + (size_t)l * TSZ;
            float2 f00 = __ldg(t + i00);
            float2 f10 = __ldg(t + i10);
            float2 f01 = __ldg(t + i01);
            float2 f11 = __ldg(t + i11);
            float omx = 1.0f - wx, omy = 1.0f - wy;
            feat[2 * l]     = (f00.x * omx + f10.x * wx) * omy + (f01.x * omx + f11.x * wx) * wy;
            feat[2 * l + 1] = (f00.y * omx + f10.y * wx) * omy + (f01.y * omx + f11.y * wx) * wy;
        }
    }

    // =======================================================================
    // PHASE 3: tiny MLP 32 -> 65, then assemble output row in shared
    // =======================================================================
    {
        u64 a3[32];
        #pragma unroll
        for (int jp = 0; jp < 32; jp++) a3[jp] = 0ull;
        float x64 = 0.0f;
        const u64* wt = reinterpret_cast<const u64*>(c_w.wt);  // stride 33 u64/row
        #pragma unroll
        for (int k = 0; k < 32; k++) {
            u64 fk = dup2(feat[k]);
            #pragma unroll
            for (int jp = 0; jp < 32; jp++) fma2(a3[jp], fk, wt[k * 33 + jp]);
            x64 += feat[k] * c_w.wt[k * 66 + 64];
        }
        float* row = so + tid * 65;
        #pragma unroll
        for (int jp = 0; jp < 32; jp++) {
            float a, b; unpack2(a3[jp], a, b);
            a += c_w.bt[2 * jp];
            b += c_w.bt[2 * jp + 1];
            if (jp == 0) {
                row[0] = (z - a) - prior;   // z - x[:,0]/SCALE - prior_z
                row[1] = b;
            } else {
                row[2 * jp]     = a;
                row[2 * jp + 1] = b;
            }
        }
        row[64] = x64 + c_w.bt[64];
    }
    __syncthreads();

    // ---- coalesced output store (float4 when the tile is full) ----
    if (cnt == 128) {
        float4* o4 = reinterpret_cast<float4*>(out + (size_t)base * 65);
        const float4* s4 = reinterpret_cast<const float4*>(so);
        #pragma unroll 4
        for (int t = tid; t < (128 * 65) / 4; t += 128) o4[t] = s4[t];
    } else {
        int tot = cnt * 65;
        for (int t = tid; t < tot; t += 128) out[(size_t)base * 65 + t] = so[t];
    }
}

// ---------------------------------------------------------------------------
// Launch
// ---------------------------------------------------------------------------
extern "C" void kernel_launch(void* const* d_in, const int* in_sizes, int n_in,
                              void* d_out, int out_size) {
    const float* inputs  = (const float*)d_in[0];
    const float* tables  = (const float*)d_in[1];
    const float* W_tiny  = (const float*)d_in[2];
    const float* b_tiny  = (const float*)d_in[3];
    const float* Wp1     = (const float*)d_in[4];
    const float* Wp2     = (const float*)d_in[5];
    const float* Wp3     = (const float*)d_in[6];
    float* out           = (float*)d_out;

    const int N = in_sizes[0] / 3;

    // Level params exactly as numpy computes them (double, libm pow/log2)
    LevelP P;
    for (int l = 0; l < NLEV; l++) {
        double sc = pow(2.0, (double)l * log2(1.5)) * 16.0 - 1.0;
        int res = (int)ceil(sc) + 1;
        P.scale[l] = (float)sc;
        P.res[l]   = res;
        P.dense[l] = ((long long)res * (long long)res <= (long long)TSZ) ? 1 : 0;
    }

    // Stage weights (padded) then copy into constant memory — all capturable
    prep_weights<<<1, 256>>>(W_tiny, b_tiny, Wp1, Wp2, Wp3);
    void *cwa = nullptr, *gwa = nullptr;
    cudaGetSymbolAddress(&cwa, c_w);
    cudaGetSymbolAddress(&gwa, g_w);
    cudaMemcpyAsync(cwa, gwa, sizeof(Weights), cudaMemcpyDeviceToDevice, 0);

    const int tiles = (N + 127) / 128;
    sdf_kernel<<<tiles, 128>>>(inputs, tables, out, N, P);
}

// round 3
// speedup vs baseline: 1.0206x; 1.0206x over previous
#include <cuda_runtime.h>
#include <cuda_bf16.h>
#include <math.h>

// ---------------------------------------------------------------------------
// Problem constants
// ---------------------------------------------------------------------------
#define NLEV 16
#define TSZ  (1 << 19)
#define TMASK (TSZ - 1)
#define HASH_PRIME 2654435761u

typedef unsigned long long u64;

// Padded weight blob (float layout identical to the shared-memory image):
//   wp1[768] | wp2[4096] | wp3[64] | wt[32*68] | bt[68]   = 7172 floats
#define OFF_WP1 0
#define OFF_WP2 768
#define OFF_WP3 4864
#define OFF_WT  4928
#define OFF_BT  7104
#define TOTW    7172

struct __align__(16) Weights {
    float wp1[12 * 64];
    float wp2[64 * 64];
    float wp3[64];
    float wt [32 * 68];   // stride 68 so every row is 16B aligned (272B)
    float bt [68];
};
__device__ Weights g_w;

struct LevelP {
    float scale[NLEV];
    int   res[NLEV];
    int   dense[NLEV];
};

// ---------------------------------------------------------------------------
// f32x2 helpers
// ---------------------------------------------------------------------------
__device__ __forceinline__ u64 dup2(float a) {
    u64 r; asm("mov.b64 %0, {%1, %1};" : "=l"(r) : "f"(a)); return r;
}
__device__ __forceinline__ void unpack2(u64 v, float &a, float &b) {
    asm("mov.b64 {%0, %1}, %2;" : "=f"(a), "=f"(b) : "l"(v));
}
__device__ __forceinline__ void fma2(u64 &d, u64 a, u64 b) {
    asm("fma.rn.f32x2 %0, %1, %2, %0;" : "+l"(d) : "l"(a), "l"(b));
}
__device__ __forceinline__ float sigm(float x) {
    return __fdividef(1.0f, 1.0f + __expf(-x));
}

// ---------------------------------------------------------------------------
// Prep kernel: pack weights into padded blob
// ---------------------------------------------------------------------------
__global__ void prep_weights(const float* __restrict__ W_tiny,
                             const float* __restrict__ b_tiny,
                             const float* __restrict__ Wp1,
                             const float* __restrict__ Wp2,
                             const float* __restrict__ Wp3) {
    int t = threadIdx.x;
    for (int i = t; i < 12 * 64; i += blockDim.x) g_w.wp1[i] = Wp1[i];
    for (int i = t; i < 64 * 64; i += blockDim.x) g_w.wp2[i] = Wp2[i];
    if (t < 64) g_w.wp3[t] = Wp3[t];
    for (int i = t; i < 32 * 68; i += blockDim.x) {
        int k = i / 68, j = i % 68;
        g_w.wt[i] = (j < 65) ? W_tiny[k * 65 + j] : 0.0f;
    }
    if (t < 68) g_w.bt[t] = (t < 65) ? b_tiny[t] : 0.0f;
}

// ---------------------------------------------------------------------------
// Fused kernel: 128 points/block, weights in SMEM, f32x2 math, LDS.128 fetch
// ---------------------------------------------------------------------------
__global__ void __launch_bounds__(128, 4)
sdf_kernel(const float* __restrict__ inputs,
           const float* __restrict__ tables,
           float* __restrict__ out,
           int N, LevelP P) {
    __shared__ float sw[TOTW];        // weights (28.7 KB)
    __shared__ float so[64 * 65];     // input staging, then half-tile output staging

    const int tid  = threadIdx.x;
    const int base = blockIdx.x * 128;
    const int cnt  = min(128, N - base);

    // ---- cooperative weight load (global -> shared, float4) ----
    {
        const float4* src = reinterpret_cast<const float4*>(g_w.wp1);
        float4* dst = reinterpret_cast<float4*>(sw);
        #pragma unroll 4
        for (int i = tid; i < TOTW / 4; i += 128) dst[i] = src[i];
    }
    // ---- coalesced input staging ----
    for (int t = tid; t < cnt * 3; t += 128) so[t] = inputs[(size_t)base * 3 + t];
    __syncthreads();
    float x = 0.f, y = 0.f, z = 0.f;
    if (tid < cnt) { x = so[tid * 3]; y = so[tid * 3 + 1]; z = so[tid * 3 + 2]; }

    // =======================================================================
    // PHASE 1: prior_net frequency encoding + 12->64 sigmoid layer
    // =======================================================================
    const float PIF = 3.14159265358979323846f;
    float enc[12];
    {
        float s, c;
        sincosf(x * PIF,          &s, &c); enc[0] = s; enc[3]  = c;
        sincosf(x * (2.0f * PIF), &s, &c); enc[1] = s; enc[4]  = c;
        sincosf(x * (4.0f * PIF), &s, &c); enc[2] = s; enc[5]  = c;
        sincosf(y * PIF,          &s, &c); enc[6] = s; enc[9]  = c;
        sincosf(y * (2.0f * PIF), &s, &c); enc[7] = s; enc[10] = c;
        sincosf(y * (4.0f * PIF), &s, &c); enc[8] = s; enc[11] = c;
    }

    float h1[64];
    {
        const ulonglong2* w1 = reinterpret_cast<const ulonglong2*>(sw + OFF_WP1);
        #pragma unroll
        for (int c = 0; c < 2; c++) {              // 2 chunks of 32 neurons
            u64 acc[16];
            #pragma unroll
            for (int q = 0; q < 16; q++) acc[q] = 0ull;
            #pragma unroll
            for (int i = 0; i < 12; i++) {
                u64 e = dup2(enc[i]);
                const ulonglong2* row = w1 + i * 16 + c * 8;
                #pragma unroll
                for (int q = 0; q < 8; q++) {
                    ulonglong2 w = row[q];         // LDS.128 broadcast
                    fma2(acc[2 * q],     e, w.x);
                    fma2(acc[2 * q + 1], e, w.y);
                }
            }
            #pragma unroll
            for (int q = 0; q < 16; q++) {
                float a, b; unpack2(acc[q], a, b);
                h1[c * 32 + 2 * q]     = sigm(a);
                h1[c * 32 + 2 * q + 1] = sigm(b);
            }
        }
    }

    // =======================================================================
    // PHASE 1b: 64->64 sigmoid layer + 64->1 dot (4 chunks of 16 neurons)
    // =======================================================================
    float prior = 0.0f;
    {
        const ulonglong2* w2 = reinterpret_cast<const ulonglong2*>(sw + OFF_WP2);
        #pragma unroll
        for (int c = 0; c < 4; c++) {
            u64 a2[8];
            #pragma unroll
            for (int q = 0; q < 8; q++) a2[q] = 0ull;
            #pragma unroll
            for (int k = 0; k < 64; k++) {
                u64 hk = dup2(h1[k]);
                const ulonglong2* row = w2 + k * 16 + c * 4;
                #pragma unroll
                for (int q = 0; q < 4; q++) {
                    ulonglong2 w = row[q];
                    fma2(a2[2 * q],     hk, w.x);
                    fma2(a2[2 * q + 1], hk, w.y);
                }
            }
            #pragma unroll
            for (int q = 0; q < 8; q++) {
                float a, b; unpack2(a2[q], a, b);
                int j = c * 16 + 2 * q;
                prior += sigm(a) * sw[OFF_WP3 + j] + sigm(b) * sw[OFF_WP3 + j + 1];
            }
        }
    }

    // =======================================================================
    // PHASE 2: multires hash-grid encode
    // =======================================================================
    float feat[32];
    {
        const float u = __fadd_rn(__fdiv_rn(x, 30.0f), 0.5f);
        const float v = __fadd_rn(__fdiv_rn(y, 30.0f), 0.5f);
        const float2* tb = reinterpret_cast<const float2*>(tables);
        #pragma unroll
        for (int l = 0; l < NLEV; l++) {
            float s  = P.scale[l];
            float px = __fadd_rn(__fmul_rn(u, s), 0.5f);
            float py = __fadd_rn(__fmul_rn(v, s), 0.5f);
            float fx = floorf(px), fy = floorf(py);
            float wx = px - fx,    wy = py - fy;
            int ix = (int)fx, iy = (int)fy;
            int i00, i10, i01, i11;
            if (P.dense[l]) {
                int r = P.res[l];
                i00 = ix + iy * r;  i10 = i00 + 1;
                i01 = i00 + r;      i11 = i01 + 1;
                i00 = min(max(i00, 0), TSZ - 1);
                i10 = min(max(i10, 0), TSZ - 1);
                i01 = min(max(i01, 0), TSZ - 1);
                i11 = min(max(i11, 0), TSZ - 1);
            } else {
                unsigned ux = (unsigned)ix, uy = (unsigned)iy;
                unsigned hy0 = uy * HASH_PRIME;
                unsigned hy1 = (uy + 1u) * HASH_PRIME;
                i00 = (int)((ux        ^ hy0) & TMASK);
                i10 = (int)(((ux + 1u) ^ hy0) & TMASK);
                i01 = (int)((ux        ^ hy1) & TMASK);
                i11 = (int)(((ux + 1u) ^ hy1) & TMASK);
            }
            const float2* t = tb + (size_t)l * TSZ;
            float2 f00 = __ldg(t + i00);
            float2 f10 = __ldg(t + i10);
            float2 f01 = __ldg(t + i01);
            float2 f11 = __ldg(t + i11);
            float omx = 1.0f - wx, omy = 1.0f - wy;
            feat[2 * l]     = (f00.x * omx + f10.x * wx) * omy + (f01.x * omx + f11.x * wx) * wy;
            feat[2 * l + 1] = (f00.y * omx + f10.y * wx) * omy + (f01.y * omx + f11.y * wx) * wy;
        }
    }

    // =======================================================================
    // PHASE 3: tiny MLP 32 -> 65 (a3 holds the output row pre-bias)
    // =======================================================================
    u64 a3[32];
    float x64 = 0.0f;
    {
        #pragma unroll
        for (int q = 0; q < 32; q++) a3[q] = 0ull;
        const ulonglong2* wt = reinterpret_cast<const ulonglong2*>(sw + OFF_WT);  // 17 ull2 / row
        #pragma unroll
        for (int k = 0; k < 32; k++) {
            u64 fk = dup2(feat[k]);
            const ulonglong2* row = wt + k * 17;
            #pragma unroll
            for (int q = 0; q < 16; q++) {
                ulonglong2 w = row[q];
                fma2(a3[2 * q],     fk, w.x);
                fma2(a3[2 * q + 1], fk, w.y);
            }
            x64 += feat[k] * sw[OFF_WT + k * 68 + 64];
        }
    }

    // =======================================================================
    // Output: two half-tile passes through 64-row staging buffer
    // =======================================================================
    #pragma unroll 1
    for (int half = 0; half < 2; half++) {
        __syncthreads();   // protects so reuse (input staging / prior half)
        const int lo = half * 64;
        if (tid >= lo && tid < lo + 64 && tid < cnt) {
            float* row = so + (tid - lo) * 65;
            #pragma unroll
            for (int q = 0; q < 32; q++) {
                float a, b; unpack2(a3[q], a, b);
                a += sw[OFF_BT + 2 * q];
                b += sw[OFF_BT + 2 * q + 1];
                if (q == 0) {
                    row[0] = (z - a) - prior;
                    row[1] = b;
                } else {
                    row[2 * q]     = a;
                    row[2 * q + 1] = b;
                }
            }
            row[64] = x64 + sw[OFF_BT + 64];
        }
        __syncthreads();
        const int rows = min(64, cnt - lo);
        if (rows == 64) {
            float4* o4 = reinterpret_cast<float4*>(out + ((size_t)base + lo) * 65);
            const float4* s4 = reinterpret_cast<const float4*>(so);
            #pragma unroll 4
            for (int t = tid; t < (64 * 65) / 4; t += 128) o4[t] = s4[t];
        } else if (rows > 0) {
            const int tot = rows * 65;
            for (int t = tid; t < tot; t += 128)
                out[((size_t)base + lo) * 65 + t] = so[t];
        }
    }
}

// ---------------------------------------------------------------------------
// Launch
// ---------------------------------------------------------------------------
extern "C" void kernel_launch(void* const* d_in, const int* in_sizes, int n_in,
                              void* d_out, int out_size) {
    const float* inputs  = (const float*)d_in[0];
    const float* tables  = (const float*)d_in[1];
    const float* W_tiny  = (const float*)d_in[2];
    const float* b_tiny  = (const float*)d_in[3];
    const float* Wp1     = (const float*)d_in[4];
    const float* Wp2     = (const float*)d_in[5];
    const float* Wp3     = (const float*)d_in[6];
    float* out           = (float*)d_out;

    const int N = in_sizes[0] / 3;

    LevelP P;
    for (int l = 0; l < NLEV; l++) {
        double sc = pow(2.0, (double)l * log2(1.5)) * 16.0 - 1.0;
        int res = (int)ceil(sc) + 1;
        P.scale[l] = (float)sc;
        P.res[l]   = res;
        P.dense[l] = ((long long)res * (long long)res <= (long long)TSZ) ? 1 : 0;
    }

    prep_weights<<<1, 256>>>(W_tiny, b_tiny, Wp1, Wp2, Wp3);

    const int tiles = (N + 127) / 128;
    sdf_kernel<<<tiles, 128>>>(inputs, tables, out, N, P);
}

// round 4
// speedup vs baseline: 1.1849x; 1.1610x over previous
#include <cuda_runtime.h>
#include <cuda_bf16.h>
#include <math.h>

// ---------------------------------------------------------------------------
// Problem constants
// ---------------------------------------------------------------------------
#define NLEV 16
#define TSZ  (1 << 19)
#define TMASK (TSZ - 1)
#define HASH_PRIME 2654435761u

typedef unsigned long long u64;

// Padded weight blob: wp1[12*64] | wp2[64*64] | wp3[64] | wt[32*68] | bt[68]
#define OFF_WP1 0
#define OFF_WP2 768
#define OFF_WP3 4864
#define OFF_WT  4928
#define OFF_BT  7104
#define TOTW    7172

struct __align__(16) Weights {
    float wp1[12 * 64];
    float wp2[64 * 64];
    float wp3[64];
    float wt [32 * 68];   // row stride 68 (16B aligned rows)
    float bt [68];
};
__device__ Weights g_w;

struct LevelP {
    float scale[NLEV];
    int   res[NLEV];
    int   dense[NLEV];
};

// Shared layout (floats)
#define ACT_STRIDE 132
#define ACT_FLOATS (64 * ACT_STRIDE)       // 8448, also holds out-stage 128*65=8320
#define PAR_STRIDE 130
#define PAR_FLOATS (16 * PAR_STRIDE)       // 2080
#define SMEM_FLOATS (TOTW + ACT_FLOATS + PAR_FLOATS + 128 + 128 + 128)
#define SMEM_BYTES  (SMEM_FLOATS * 4)

// ---------------------------------------------------------------------------
// f32x2 helpers
// ---------------------------------------------------------------------------
__device__ __forceinline__ u64 dup2(float a) {
    u64 r; asm("mov.b64 %0, {%1, %1};" : "=l"(r) : "f"(a)); return r;
}
__device__ __forceinline__ u64 pack2(float a, float b) {
    u64 r; asm("mov.b64 %0, {%1, %2};" : "=l"(r) : "f"(a), "f"(b)); return r;
}
__device__ __forceinline__ void unpack2(u64 v, float &a, float &b) {
    asm("mov.b64 {%0, %1}, %2;" : "=f"(a), "=f"(b) : "l"(v));
}
__device__ __forceinline__ void fma2(u64 &d, u64 a, u64 b) {
    asm("fma.rn.f32x2 %0, %1, %2, %0;" : "+l"(d) : "l"(a), "l"(b));
}
__device__ __forceinline__ float sigm(float x) {
    return __fdividef(1.0f, 1.0f + __expf(-x));
}

// ---------------------------------------------------------------------------
// Register-tiled GEMM accumulate:
//   C[128 pts][64 cols] += A_T[K][128] * B[K][64-of-NC]
// Thread (pg,cg) owns points [pg*16, +16) x cols [cg*4, +4).
// acc[p2*4 + c] is a u64 packing points (2*p2, 2*p2+1) for col c.
// ---------------------------------------------------------------------------
template <int K, int NC>
__device__ __forceinline__ void gemm_acc(u64* __restrict__ acc,
                                         const float* __restrict__ aT,
                                         const float* __restrict__ B,
                                         int pg, int cg) {
    const float* arow = aT + pg * 16;
    const float* brow = B + cg * 4;
    #pragma unroll 16
    for (int k = 0; k < K; k++) {
        ulonglong2 a01 = *reinterpret_cast<const ulonglong2*>(arow);
        ulonglong2 a23 = *reinterpret_cast<const ulonglong2*>(arow + 4);
        ulonglong2 a45 = *reinterpret_cast<const ulonglong2*>(arow + 8);
        ulonglong2 a67 = *reinterpret_cast<const ulonglong2*>(arow + 12);
        float4 b4 = *reinterpret_cast<const float4*>(brow);
        u64 b0 = dup2(b4.x), b1 = dup2(b4.y), b2 = dup2(b4.z), b3 = dup2(b4.w);
        u64 a[8] = {a01.x, a01.y, a23.x, a23.y, a45.x, a45.y, a67.x, a67.y};
        #pragma unroll
        for (int p = 0; p < 8; p++) {
            fma2(acc[p * 4 + 0], a[p], b0);
            fma2(acc[p * 4 + 1], a[p], b1);
            fma2(acc[p * 4 + 2], a[p], b2);
            fma2(acc[p * 4 + 3], a[p], b3);
        }
        arow += ACT_STRIDE;
        brow += NC;
    }
}

// ---------------------------------------------------------------------------
// Prep kernel: pack weights into padded blob
// ---------------------------------------------------------------------------
__global__ void prep_weights(const float* __restrict__ W_tiny,
                             const float* __restrict__ b_tiny,
                             const float* __restrict__ Wp1,
                             const float* __restrict__ Wp2,
                             const float* __restrict__ Wp3) {
    int t = threadIdx.x;
    for (int i = t; i < 12 * 64; i += blockDim.x) g_w.wp1[i] = Wp1[i];
    for (int i = t; i < 64 * 64; i += blockDim.x) g_w.wp2[i] = Wp2[i];
    if (t < 64) g_w.wp3[t] = Wp3[t];
    for (int i = t; i < 32 * 68; i += blockDim.x) {
        int k = i / 68, j = i % 68;
        g_w.wt[i] = (j < 65) ? W_tiny[k * 65 + j] : 0.0f;
    }
    if (t < 68) g_w.bt[t] = (t < 65) ? b_tiny[t] : 0.0f;
}

// ---------------------------------------------------------------------------
// Fused kernel: 128-point tile, GEMM-tiled MLPs, scalar hash phase
// ---------------------------------------------------------------------------
__global__ void __launch_bounds__(128)
sdf_kernel(const float* __restrict__ inputs,
           const float* __restrict__ tables,
           float* __restrict__ out,
           int N, LevelP P) {
    extern __shared__ float smem[];
    float* sw   = smem;                       // weights blob
    float* actT = sw + TOTW;                  // encT / h1T / featT / out-stage
    float* sPar = actT + ACT_FLOATS;          // [16][130] prior partials
    float* sZ   = sPar + PAR_FLOATS;          // [128]
    float* sX64 = sZ + 128;                   // [128]
    float* sPZ  = sX64 + 128;                 // [128]

    const int tid = threadIdx.x;
    const int pg  = tid >> 4;                 // point group (16 pts)
    const int cg  = tid & 15;                 // col group (4 cols)
    const int base = blockIdx.x * 128;
    const int cnt  = min(128, N - base);

    // ---- cooperative weight load + input staging ----
    {
        const float4* src = reinterpret_cast<const float4*>(g_w.wp1);
        float4* dst = reinterpret_cast<float4*>(sw);
        #pragma unroll 4
        for (int i = tid; i < TOTW / 4; i += 128) dst[i] = src[i];
    }
    for (int t = tid; t < cnt * 3; t += 128) actT[t] = inputs[(size_t)base * 3 + t];
    __syncthreads();
    float x = 0.f, y = 0.f, z = 0.f;
    if (tid < cnt) { x = actT[tid * 3]; y = actT[tid * 3 + 1]; z = actT[tid * 3 + 2]; }
    __syncthreads();                          // actT now reused as encT

    // =======================================================================
    // Scalar phase A: frequency encoding -> encT[12][128], z -> sZ
    // =======================================================================
    {
        const float PIF = 3.14159265358979323846f;
        float s, c;
        float e[12];
        sincosf(x * PIF,          &s, &c); e[0] = s; e[3]  = c;
        sincosf(x * (2.0f * PIF), &s, &c); e[1] = s; e[4]  = c;
        sincosf(x * (4.0f * PIF), &s, &c); e[2] = s; e[5]  = c;
        sincosf(y * PIF,          &s, &c); e[6] = s; e[9]  = c;
        sincosf(y * (2.0f * PIF), &s, &c); e[7] = s; e[10] = c;
        sincosf(y * (4.0f * PIF), &s, &c); e[8] = s; e[11] = c;
        #pragma unroll
        for (int i = 0; i < 12; i++) actT[i * ACT_STRIDE + tid] = (tid < cnt) ? e[i] : 0.0f;
        sZ[tid] = z;
    }
    __syncthreads();

    u64 acc[32];

    // =======================================================================
    // GEMM1: h1 = sigmoid(enc @ Wp1)   [128,12]x[12,64]
    // =======================================================================
    #pragma unroll
    for (int q = 0; q < 32; q++) acc[q] = 0ull;
    gemm_acc<12, 64>(acc, actT, sw + OFF_WP1, pg, cg);
    __syncthreads();                          // done reading encT
    // sigmoid + transposed store: h1T[col][pt]
    #pragma unroll
    for (int c = 0; c < 4; c++) {
        float* row = actT + (cg * 4 + c) * ACT_STRIDE + pg * 16;
        #pragma unroll
        for (int p2 = 0; p2 < 8; p2++) {
            float a, b; unpack2(acc[p2 * 4 + c], a, b);
            *reinterpret_cast<u64*>(row + 2 * p2) = pack2(sigm(a), sigm(b));
        }
    }
    __syncthreads();

    // =======================================================================
    // GEMM2: h2 = sigmoid(h1 @ Wp2); prior partials = sum_j h2[:,j]*wp3[j]
    // =======================================================================
    #pragma unroll
    for (int q = 0; q < 32; q++) acc[q] = 0ull;
    gemm_acc<64, 64>(acc, actT, sw + OFF_WP2, pg, cg);
    {
        float partA[8], partB[8];
        #pragma unroll
        for (int p2 = 0; p2 < 8; p2++) { partA[p2] = 0.f; partB[p2] = 0.f; }
        #pragma unroll
        for (int c = 0; c < 4; c++) {
            float w3 = sw[OFF_WP3 + cg * 4 + c];
            #pragma unroll
            for (int p2 = 0; p2 < 8; p2++) {
                float a, b; unpack2(acc[p2 * 4 + c], a, b);
                partA[p2] += sigm(a) * w3;
                partB[p2] += sigm(b) * w3;
            }
        }
        float* prow = sPar + cg * PAR_STRIDE + pg * 16;
        #pragma unroll
        for (int p2 = 0; p2 < 8; p2++)
            *reinterpret_cast<u64*>(prow + 2 * p2) = pack2(partA[p2], partB[p2]);
    }
    __syncthreads();                          // done reading h1T; sPar ready

    // =======================================================================
    // Scalar phase B: hash encode -> featT[32][128], x64 dot, sPZ
    // =======================================================================
    {
        float feat[32];
        float x64 = 0.0f;
        if (tid < cnt) {
            const float u = __fadd_rn(__fdiv_rn(x, 30.0f), 0.5f);
            const float v = __fadd_rn(__fdiv_rn(y, 30.0f), 0.5f);
            const float2* tb = reinterpret_cast<const float2*>(tables);
            #pragma unroll
            for (int l = 0; l < NLEV; l++) {
                float s  = P.scale[l];
                float px = __fadd_rn(__fmul_rn(u, s), 0.5f);
                float py = __fadd_rn(__fmul_rn(v, s), 0.5f);
                float fx = floorf(px), fy = floorf(py);
                float wx = px - fx,    wy = py - fy;
                int ix = (int)fx, iy = (int)fy;
                int i00, i10, i01, i11;
                if (P.dense[l]) {
                    int r = P.res[l];
                    i00 = ix + iy * r;  i10 = i00 + 1;
                    i01 = i00 + r;      i11 = i01 + 1;
                    i00 = min(max(i00, 0), TSZ - 1);
                    i10 = min(max(i10, 0), TSZ - 1);
                    i01 = min(max(i01, 0), TSZ - 1);
                    i11 = min(max(i11, 0), TSZ - 1);
                } else {
                    unsigned ux = (unsigned)ix, uy = (unsigned)iy;
                    unsigned hy0 = uy * HASH_PRIME;
                    unsigned hy1 = (uy + 1u) * HASH_PRIME;
                    i00 = (int)((ux        ^ hy0) & TMASK);
                    i10 = (int)(((ux + 1u) ^ hy0) & TMASK);
                    i01 = (int)((ux        ^ hy1) & TMASK);
                    i11 = (int)(((ux + 1u) ^ hy1) & TMASK);
                }
                const float2* t = tb + (size_t)l * TSZ;
                float2 f00 = __ldg(t + i00);
                float2 f10 = __ldg(t + i10);
                float2 f01 = __ldg(t + i01);
                float2 f11 = __ldg(t + i11);
                float omx = 1.0f - wx, omy = 1.0f - wy;
                feat[2 * l]     = (f00.x * omx + f10.x * wx) * omy + (f01.x * omx + f11.x * wx) * wy;
                feat[2 * l + 1] = (f00.y * omx + f10.y * wx) * omy + (f01.y * omx + f11.y * wx) * wy;
            }
        } else {
            #pragma unroll
            for (int k = 0; k < 32; k++) feat[k] = 0.0f;
        }
        #pragma unroll
        for (int k = 0; k < 32; k++) {
            actT[k * ACT_STRIDE + tid] = feat[k];     // featT (rows 0..31)
            x64 += feat[k] * sw[OFF_WT + k * 68 + 64];
        }
        sX64[tid] = x64 + sw[OFF_BT + 64];
        // prior reduction + fold z and bias0
        float pr = 0.0f;
        #pragma unroll
        for (int c = 0; c < 16; c++) pr += sPar[c * PAR_STRIDE + tid];
        sPZ[tid] = (sZ[tid] - sw[OFF_BT]) - pr;       // z - bt0 - prior
    }
    __syncthreads();

    // =======================================================================
    // GEMM3: x[:,0:64] = feat @ wt[:,0:64]   [128,32]x[32,64]
    // =======================================================================
    #pragma unroll
    for (int q = 0; q < 32; q++) acc[q] = 0ull;
    gemm_acc<32, 68>(acc, actT, sw + OFF_WT, pg, cg);
    __syncthreads();                          // featT dead; actT -> out stage

    // ---- assemble output rows [128][65] in shared ----
    {
        float* ost = actT;
        #pragma unroll
        for (int c = 0; c < 4; c++) {
            const int col = cg * 4 + c;
            const float bias = sw[OFF_BT + col];
            #pragma unroll
            for (int p2 = 0; p2 < 8; p2++) {
                float a, b; unpack2(acc[p2 * 4 + c], a, b);
                int pA = pg * 16 + 2 * p2;
                if (col == 0) {
                    ost[pA * 65]        = sPZ[pA] - a;
                    ost[(pA + 1) * 65]  = sPZ[pA + 1] - b;
                } else {
                    ost[pA * 65 + col]       = a + bias;
                    ost[(pA + 1) * 65 + col] = b + bias;
                }
            }
        }
        ost[tid * 65 + 64] = sX64[tid];
    }
    __syncthreads();

    // ---- coalesced flush ----
    if (cnt == 128) {
        float4* o4 = reinterpret_cast<float4*>(out + (size_t)base * 65);
        const float4* s4 = reinterpret_cast<const float4*>(actT);
        #pragma unroll 4
        for (int t = tid; t < (128 * 65) / 4; t += 128) o4[t] = s4[t];
    } else if (cnt > 0) {
        const int tot = cnt * 65;
        for (int t = tid; t < tot; t += 128) out[(size_t)base * 65 + t] = actT[t];
    }
}

// ---------------------------------------------------------------------------
// Launch
// ---------------------------------------------------------------------------
extern "C" void kernel_launch(void* const* d_in, const int* in_sizes, int n_in,
                              void* d_out, int out_size) {
    const float* inputs  = (const float*)d_in[0];
    const float* tables  = (const float*)d_in[1];
    const float* W_tiny  = (const float*)d_in[2];
    const float* b_tiny  = (const float*)d_in[3];
    const float* Wp1     = (const float*)d_in[4];
    const float* Wp2     = (const float*)d_in[5];
    const float* Wp3     = (const float*)d_in[6];
    float* out           = (float*)d_out;

    const int N = in_sizes[0] / 3;

    LevelP P;
    for (int l = 0; l < NLEV; l++) {
        double sc = pow(2.0, (double)l * log2(1.5)) * 16.0 - 1.0;
        int res = (int)ceil(sc) + 1;
        P.scale[l] = (float)sc;
        P.res[l]   = res;
        P.dense[l] = ((long long)res * (long long)res <= (long long)TSZ) ? 1 : 0;
    }

    prep_weights<<<1, 256>>>(W_tiny, b_tiny, Wp1, Wp2, Wp3);

    static int attr_done = 0;
    if (!attr_done) {
        cudaFuncSetAttribute(sdf_kernel,
                             cudaFuncAttributeMaxDynamicSharedMemorySize, SMEM_BYTES);
        attr_done = 1;
    }

    const int tiles = (N + 127) / 128;
    sdf_kernel<<<tiles, 128, SMEM_BYTES>>>(inputs, tables, out, N, P);
}

// round 5
// speedup vs baseline: 1.2828x; 1.0826x over previous
#include <cuda_runtime.h>
#include <cuda_bf16.h>
#include <math.h>

// ---------------------------------------------------------------------------
// Problem constants
// ---------------------------------------------------------------------------
#define NLEV 16
#define TSZ  (1 << 19)
#define TMASK (TSZ - 1)
#define HASH_PRIME 2654435761u

typedef unsigned long long u64;

// Padded weight blob: wp1[12*64] | wp2[64*64] | wp3[64] | wt[32*68] | bt[68]
#define OFF_WP1 0
#define OFF_WP2 768
#define OFF_WP3 4864
#define OFF_WT  4928
#define OFF_BT  7104
#define TOTW    7172

struct __align__(16) Weights {
    float wp1[12 * 64];
    float wp2[64 * 64];
    float wp3[64];
    float wt [32 * 68];   // row stride 68 (16B aligned rows)
    float bt [68];
};
__device__ Weights g_w;

struct LevelP {
    float scale[NLEV];
    int   res[NLEV];
    int   dense[NLEV];
};

// Shared layout (floats)
#define ACT_STRIDE 132
#define ACT_FLOATS  (64 * ACT_STRIDE)     // 8448 (encT/h1T, then out-stage 128*65=8320)
#define FEAT_FLOATS (32 * ACT_STRIDE)     // 4224
#define PAR_STRIDE 130
#define PAR_FLOATS (16 * PAR_STRIDE)      // 2080 (also input staging 384)
#define SMEM_FLOATS (TOTW + ACT_FLOATS + FEAT_FLOATS + PAR_FLOATS + 128 + 128 + 128)
#define SMEM_BYTES  (SMEM_FLOATS * 4)

// ---------------------------------------------------------------------------
// f32x2 helpers
// ---------------------------------------------------------------------------
__device__ __forceinline__ u64 dup2(float a) {
    u64 r; asm("mov.b64 %0, {%1, %1};" : "=l"(r) : "f"(a)); return r;
}
__device__ __forceinline__ u64 pack2(float a, float b) {
    u64 r; asm("mov.b64 %0, {%1, %2};" : "=l"(r) : "f"(a), "f"(b)); return r;
}
__device__ __forceinline__ void unpack2(u64 v, float &a, float &b) {
    asm("mov.b64 {%0, %1}, %2;" : "=f"(a), "=f"(b) : "l"(v));
}
__device__ __forceinline__ void fma2(u64 &d, u64 a, u64 b) {
    asm("fma.rn.f32x2 %0, %1, %2, %0;" : "+l"(d) : "l"(a), "l"(b));
}
__device__ __forceinline__ float sigm(float x) {
    return __fdividef(1.0f, 1.0f + __expf(-x));
}

// ---------------------------------------------------------------------------
// Register-tiled GEMM accumulate with k+1 prefetch (LDS latency hiding):
//   C[128 pts][64 cols] += A_T[K][128] * B[K][NC-of-64+]
// Thread (pg,cg): points [pg*8,+8) x cols [cg*4,+4).
// acc[p2*4+c] packs points (pg*8+2p2, +1) for col cg*4+c.
// NOTE: prefetch reads one row past K — always lands in valid smem (value unused).
// ---------------------------------------------------------------------------
template <int K, int NC>
__device__ __forceinline__ void gemm_acc(u64* __restrict__ acc,
                                         const float* __restrict__ aT,
                                         const float* __restrict__ B,
                                         int pg, int cg) {
    const float* arow = aT + pg * 8;
    const float* brow = B + cg * 4;
    ulonglong2 a01 = *reinterpret_cast<const ulonglong2*>(arow);
    ulonglong2 a23 = *reinterpret_cast<const ulonglong2*>(arow + 4);
    float4 b4 = *reinterpret_cast<const float4*>(brow);
    #pragma unroll 8
    for (int k = 0; k < K; k++) {
        const float* an = arow + (k + 1) * ACT_STRIDE;      // prefetch next k
        ulonglong2 na01 = *reinterpret_cast<const ulonglong2*>(an);
        ulonglong2 na23 = *reinterpret_cast<const ulonglong2*>(an + 4);
        float4 nb4 = *reinterpret_cast<const float4*>(brow + (k + 1) * NC);
        u64 b0 = dup2(b4.x), b1 = dup2(b4.y), b2 = dup2(b4.z), b3 = dup2(b4.w);
        u64 a0 = a01.x, a1 = a01.y, a2 = a23.x, a3 = a23.y;
        fma2(acc[0],  a0, b0); fma2(acc[1],  a0, b1); fma2(acc[2],  a0, b2); fma2(acc[3],  a0, b3);
        fma2(acc[4],  a1, b0); fma2(acc[5],  a1, b1); fma2(acc[6],  a1, b2); fma2(acc[7],  a1, b3);
        fma2(acc[8],  a2, b0); fma2(acc[9],  a2, b1); fma2(acc[10], a2, b2); fma2(acc[11], a2, b3);
        fma2(acc[12], a3, b0); fma2(acc[13], a3, b1); fma2(acc[14], a3, b2); fma2(acc[15], a3, b3);
        a01 = na01; a23 = na23; b4 = nb4;
    }
}

// ---------------------------------------------------------------------------
// Prep kernel: pack weights into padded blob
// ---------------------------------------------------------------------------
__global__ void prep_weights(const float* __restrict__ W_tiny,
                             const float* __restrict__ b_tiny,
                             const float* __restrict__ Wp1,
                             const float* __restrict__ Wp2,
                             const float* __restrict__ Wp3) {
    int t = threadIdx.x;
    for (int i = t; i < 12 * 64; i += blockDim.x) g_w.wp1[i] = Wp1[i];
    for (int i = t; i < 64 * 64; i += blockDim.x) g_w.wp2[i] = Wp2[i];
    if (t < 64) g_w.wp3[t] = Wp3[t];
    for (int i = t; i < 32 * 68; i += blockDim.x) {
        int k = i / 68, j = i % 68;
        g_w.wt[i] = (j < 65) ? W_tiny[k * 65 + j] : 0.0f;
    }
    if (t < 68) g_w.bt[t] = (t < 65) ? b_tiny[t] : 0.0f;
}

// ---------------------------------------------------------------------------
// Fused kernel: 128-pt tile, 256 threads, split scalar phase, pipelined GEMMs
// ---------------------------------------------------------------------------
__global__ void __launch_bounds__(256, 2)
sdf_kernel(const float* __restrict__ inputs,
           const float* __restrict__ tables,
           float* __restrict__ out,
           int N, LevelP P) {
    extern __shared__ float smem[];
    float* sw    = smem;                      // weights blob (28.7 KB)
    float* actT  = sw + TOTW;                 // encT rows 0-11 / h1T rows 0-63 / out-stage
    float* featT = actT + ACT_FLOATS;         // [32][132]
    float* sPar  = featT + FEAT_FLOATS;       // [16][130] prior partials (+input staging)
    float* sZ    = sPar + PAR_FLOATS;         // [128]
    float* sX64  = sZ + 128;                  // [128]
    float* sPZ   = sX64 + 128;                // [128]

    const int tid = threadIdx.x;
    const int pg  = tid >> 4;                 // 16 point-groups of 8 pts
    const int cg  = tid & 15;                 // 16 col-groups of 4 cols
    const int base = blockIdx.x * 128;
    const int cnt  = min(128, N - base);

    // ---- cooperative weight load + input staging (into sPar region) ----
    {
        const float4* src = reinterpret_cast<const float4*>(g_w.wp1);
        float4* dst = reinterpret_cast<float4*>(sw);
        #pragma unroll
        for (int i = tid; i < TOTW / 4; i += 256) dst[i] = src[i];
    }
    for (int t = tid; t < cnt * 3; t += 256) sPar[t] = inputs[(size_t)base * 3 + t];
    __syncthreads();

    // =======================================================================
    // Split scalar phase: warps 0-3 frequency-encode; warps 4-7 hash-gather
    // =======================================================================
    if (tid < 128) {
        const float x = sPar[tid * 3], y = sPar[tid * 3 + 1], z = sPar[tid * 3 + 2];
        const float PIF = 3.14159265358979323846f;
        float s, c, e[12];
        sincosf(x * PIF,          &s, &c); e[0] = s; e[3]  = c;
        sincosf(x * (2.0f * PIF), &s, &c); e[1] = s; e[4]  = c;
        sincosf(x * (4.0f * PIF), &s, &c); e[2] = s; e[5]  = c;
        sincosf(y * PIF,          &s, &c); e[6] = s; e[9]  = c;
        sincosf(y * (2.0f * PIF), &s, &c); e[7] = s; e[10] = c;
        sincosf(y * (4.0f * PIF), &s, &c); e[8] = s; e[11] = c;
        #pragma unroll
        for (int i = 0; i < 12; i++) actT[i * ACT_STRIDE + tid] = (tid < cnt) ? e[i] : 0.0f;
        sZ[tid] = z;
    } else {
        const int p = tid - 128;
        const float x = sPar[p * 3], y = sPar[p * 3 + 1];
        float feat[32];
        float x64 = 0.0f;
        if (p < cnt) {
            const float u = __fadd_rn(__fdiv_rn(x, 30.0f), 0.5f);
            const float v = __fadd_rn(__fdiv_rn(y, 30.0f), 0.5f);
            const float2* tb = reinterpret_cast<const float2*>(tables);
            #pragma unroll
            for (int l = 0; l < NLEV; l++) {
                float s  = P.scale[l];
                float px = __fadd_rn(__fmul_rn(u, s), 0.5f);
                float py = __fadd_rn(__fmul_rn(v, s), 0.5f);
                float fx = floorf(px), fy = floorf(py);
                float wx = px - fx,    wy = py - fy;
                int ix = (int)fx, iy = (int)fy;
                int i00, i10, i01, i11;
                if (P.dense[l]) {
                    int r = P.res[l];
                    i00 = ix + iy * r;  i10 = i00 + 1;
                    i01 = i00 + r;      i11 = i01 + 1;
                    i00 = min(max(i00, 0), TSZ - 1);
                    i10 = min(max(i10, 0), TSZ - 1);
                    i01 = min(max(i01, 0), TSZ - 1);
                    i11 = min(max(i11, 0), TSZ - 1);
                } else {
                    unsigned ux = (unsigned)ix, uy = (unsigned)iy;
                    unsigned hy0 = uy * HASH_PRIME;
                    unsigned hy1 = (uy + 1u) * HASH_PRIME;
                    i00 = (int)((ux        ^ hy0) & TMASK);
                    i10 = (int)(((ux + 1u) ^ hy0) & TMASK);
                    i01 = (int)((ux        ^ hy1) & TMASK);
                    i11 = (int)(((ux + 1u) ^ hy1) & TMASK);
                }
                const float2* t = tb + (size_t)l * TSZ;
                float2 f00 = __ldg(t + i00);
                float2 f10 = __ldg(t + i10);
                float2 f01 = __ldg(t + i01);
                float2 f11 = __ldg(t + i11);
                float omx = 1.0f - wx, omy = 1.0f - wy;
                feat[2 * l]     = (f00.x * omx + f10.x * wx) * omy + (f01.x * omx + f11.x * wx) * wy;
                feat[2 * l + 1] = (f00.y * omx + f10.y * wx) * omy + (f01.y * omx + f11.y * wx) * wy;
            }
        } else {
            #pragma unroll
            for (int k = 0; k < 32; k++) feat[k] = 0.0f;
        }
        #pragma unroll
        for (int k = 0; k < 32; k++) {
            featT[k * ACT_STRIDE + p] = feat[k];
            x64 += feat[k] * sw[OFF_WT + k * 68 + 64];
        }
        sX64[p] = x64 + sw[OFF_BT + 64];
    }
    __syncthreads();

    u64 acc[16];

    // ---- GEMM1: h1 = sigmoid(enc @ Wp1)  [128,12]x[12,64] ----
    #pragma unroll
    for (int q = 0; q < 16; q++) acc[q] = 0ull;
    gemm_acc<12, 64>(acc, actT, sw + OFF_WP1, pg, cg);
    __syncthreads();                          // encT reads done; actT -> h1T
    #pragma unroll
    for (int c = 0; c < 4; c++) {
        float* row = actT + (cg * 4 + c) * ACT_STRIDE + pg * 8;
        #pragma unroll
        for (int p2 = 0; p2 < 4; p2++) {
            float a, b; unpack2(acc[p2 * 4 + c], a, b);
            *reinterpret_cast<u64*>(row + 2 * p2) = pack2(sigm(a), sigm(b));
        }
    }
    __syncthreads();

    // ---- GEMM2: h2 = sigmoid(h1 @ Wp2); prior partials via wp3 ----
    #pragma unroll
    for (int q = 0; q < 16; q++) acc[q] = 0ull;
    gemm_acc<64, 64>(acc, actT, sw + OFF_WP2, pg, cg);
    {
        float* prow = sPar + cg * PAR_STRIDE + pg * 8;
        #pragma unroll
        for (int p2 = 0; p2 < 4; p2++) {
            float pa = 0.f, pb = 0.f;
            #pragma unroll
            for (int c = 0; c < 4; c++) {
                float w3 = sw[OFF_WP3 + cg * 4 + c];
                float a, b; unpack2(acc[p2 * 4 + c], a, b);
                pa += sigm(a) * w3;
                pb += sigm(b) * w3;
            }
            *reinterpret_cast<u64*>(prow + 2 * p2) = pack2(pa, pb);
        }
    }
    __syncthreads();                          // h1T reads done; sPar ready

    // ---- prior reduction (half threads) + GEMM3: feat @ wt[:,0:64] ----
    if (tid < 128) {
        float pr = 0.0f;
        #pragma unroll
        for (int c = 0; c < 16; c++) pr += sPar[c * PAR_STRIDE + tid];
        sPZ[tid] = (sZ[tid] - sw[OFF_BT]) - pr;   // z - bt0 - prior
    }
    #pragma unroll
    for (int q = 0; q < 16; q++) acc[q] = 0ull;
    gemm_acc<32, 68>(acc, featT, sw + OFF_WT, pg, cg);
    __syncthreads();                          // featT/h1T dead; sPZ ready; actT -> out

    // ---- assemble output rows [128][65] in shared ----
    {
        float* ost = actT;
        #pragma unroll
        for (int c = 0; c < 4; c++) {
            const int col = cg * 4 + c;
            const float bias = sw[OFF_BT + col];
            #pragma unroll
            for (int p2 = 0; p2 < 4; p2++) {
                float a, b; unpack2(acc[p2 * 4 + c], a, b);
                int pA = pg * 8 + 2 * p2;
                if (col == 0) {
                    ost[pA * 65]       = sPZ[pA] - a;
                    ost[(pA + 1) * 65] = sPZ[pA + 1] - b;
                } else {
                    ost[pA * 65 + col]       = a + bias;
                    ost[(pA + 1) * 65 + col] = b + bias;
                }
            }
        }
        if (tid < 128) ost[tid * 65 + 64] = sX64[tid];
    }
    __syncthreads();

    // ---- coalesced flush ----
    if (cnt == 128) {
        float4* o4 = reinterpret_cast<float4*>(out + (size_t)base * 65);
        const float4* s4 = reinterpret_cast<const float4*>(actT);
        #pragma unroll
        for (int t = tid; t < (128 * 65) / 4; t += 256) o4[t] = s4[t];
    } else if (cnt > 0) {
        const int tot = cnt * 65;
        for (int t = tid; t < tot; t += 256) out[(size_t)base * 65 + t] = actT[t];
    }
}

// ---------------------------------------------------------------------------
// Launch
// ---------------------------------------------------------------------------
extern "C" void kernel_launch(void* const* d_in, const int* in_sizes, int n_in,
                              void* d_out, int out_size) {
    const float* inputs  = (const float*)d_in[0];
    const float* tables  = (const float*)d_in[1];
    const float* W_tiny  = (const float*)d_in[2];
    const float* b_tiny  = (const float*)d_in[3];
    const float* Wp1     = (const float*)d_in[4];
    const float* Wp2     = (const float*)d_in[5];
    const float* Wp3     = (const float*)d_in[6];
    float* out           = (float*)d_out;

    const int N = in_sizes[0] / 3;

    LevelP P;
    for (int l = 0; l < NLEV; l++) {
        double sc = pow(2.0, (double)l * log2(1.5)) * 16.0 - 1.0;
        int res = (int)ceil(sc) + 1;
        P.scale[l] = (float)sc;
        P.res[l]   = res;
        P.dense[l] = ((long long)res * (long long)res <= (long long)TSZ) ? 1 : 0;
    }

    prep_weights<<<1, 256>>>(W_tiny, b_tiny, Wp1, Wp2, Wp3);

    static int attr_done = 0;
    if (!attr_done) {
        cudaFuncSetAttribute(sdf_kernel,
                             cudaFuncAttributeMaxDynamicSharedMemorySize, SMEM_BYTES);
        attr_done = 1;
    }

    const int tiles = (N + 127) / 128;
    sdf_kernel<<<tiles, 256, SMEM_BYTES>>>(inputs, tables, out, N, P);
}